// round 10
// baseline (speedup 1.0000x reference)
#include <cuda_runtime.h>
#include <math.h>
#include <stdint.h>

#define DD   768
#define MAXK 150
#define MAXN 1500
#define MAXB 256
#define MAXM 256
#define BETA_C 0.1f

// ---- scratch (static device globals; no allocation) ----
__device__ float g_Rh[(size_t)MAXK * DD * DD];   // tf32-hi rotate matrices
__device__ float g_Rl[(size_t)MAXK * DD * DD];   // tf32-lo residuals
__device__ float g_Bh[(size_t)MAXK * MAXM * DD]; // pre-split B (hi)
__device__ float g_Bl[(size_t)MAXK * MAXM * DD]; // pre-split B (lo)
__device__ float g_c2[MAXN];
__device__ float g_dotin[MAXB * MAXN];
__device__ float g_dotood[MAXM * MAXN];
__device__ int   g_cnt[MAXK];
__device__ int   g_clist[MAXK * MAXN];
__device__ int   g_ballin[MAXB];
__device__ float g_din[MAXB];
__device__ float g_dnear[MAXK * MAXM];
__device__ float g_euc2ood[MAXK * MAXM];
__device__ float g_eucin2[MAXB];

// ======================= helpers ===========================================
__device__ __forceinline__ uint32_t smem_to_u32(const void* p) {
    uint32_t a;
    asm("{ .reg .u64 t; cvta.to.shared.u64 t, %1; cvt.u32.u64 %0, t; }" : "=r"(a) : "l"(p));
    return a;
}
__device__ __forceinline__ uint32_t tf32_of(float x) {
    uint32_t h;
    asm("cvt.rna.tf32.f32 %0, %1;" : "=r"(h) : "f"(x));
    return h;
}
__device__ __forceinline__ void split_tf32(float x, float& hi, float& lo) {
    hi = __uint_as_float(tf32_of(x));
    lo = __uint_as_float(tf32_of(x - hi));
}
__device__ __forceinline__ void split4(float4 v, float4& h, float4& l) {
    split_tf32(v.x, h.x, l.x);
    split_tf32(v.y, h.y, l.y);
    split_tf32(v.z, h.z, l.z);
    split_tf32(v.w, h.w, l.w);
}
__device__ __forceinline__ void mma_tf32(float* d, const uint32_t* a, const uint32_t* b) {
    asm volatile(
        "mma.sync.aligned.m16n8k8.row.col.f32.tf32.tf32.f32 "
        "{%0,%1,%2,%3}, {%4,%5,%6,%7}, {%8,%9}, {%0,%1,%2,%3};"
        : "+f"(d[0]), "+f"(d[1]), "+f"(d[2]), "+f"(d[3])
        : "r"(a[0]), "r"(a[1]), "r"(a[2]), "r"(a[3]), "r"(b[0]), "r"(b[1]));
}
__device__ __forceinline__ void cp16(uint32_t dst, const void* src) {
    asm volatile("cp.async.cg.shared.global [%0], [%1], 16;" :: "r"(dst), "l"(src));
}
#define CP_COMMIT() asm volatile("cp.async.commit_group;" ::: "memory")
#define CP_WAIT1()  asm volatile("cp.async.wait_group 1;" ::: "memory")
#define CP_WAIT0()  asm volatile("cp.async.wait_group 0;" ::: "memory")

// ======================= setup kernels =====================================
// one block: zero counts + build class->ball lists
__global__ void abl_clist_all(const int* __restrict__ blab, int N, int K) {
    int t = threadIdx.x;
    for (int i = t; i < K; i += 256) g_cnt[i] = 0;
    __syncthreads();
    for (int n = t; n < N; n += 256) {
        int kk = blab[n];
        int pos = atomicAdd(&g_cnt[kk], 1);
        g_clist[kk * MAXN + pos] = n;
    }
}

// build pre-split R (hi/lo) from packed L/U/Dd
__global__ void abl_build_Rsplit(const float* __restrict__ L, const float* __restrict__ U,
                                 const float* __restrict__ Ddm, int NTRI) {
    int k = blockIdx.y;
    int tidx = blockIdx.x;
    int ti = 0;
    while ((ti + 1) * (ti + 2) / 2 <= tidx) ti++;
    int tj = tidx - ti * (ti + 1) / 2;

    const float* Lk = L + (size_t)k * NTRI;
    const float* Uk = U + (size_t)k * NTRI;
    float* Rh = g_Rh + (size_t)k * DD * DD;
    float* Rl = g_Rl + (size_t)k * DD * DD;

    __shared__ float su[32][33];
    int tx = threadIdx.x & 31, ty = threadIdx.x >> 5;
#pragma unroll
    for (int s = 0; s < 4; s++) {
        int ry = ty + 8 * s;
        int r = ti * 32 + ry, c = tj * 32 + tx;
        if (r > c) {
            size_t p = (size_t)r * (r - 1) / 2 + c;
            float v = Lk[p], h, l;
            split_tf32(v, h, l);
            Rh[(size_t)r * DD + c] = h;
            Rl[(size_t)r * DD + c] = l;
            su[ry][tx] = Uk[p];
        } else if (r == c) {
            float v = Ddm[(size_t)k * DD + r], h, l;
            split_tf32(v, h, l);
            Rh[(size_t)r * DD + c] = h;
            Rl[(size_t)r * DD + c] = l;
        }
    }
    __syncthreads();
#pragma unroll
    for (int s = 0; s < 4; s++) {
        int ry = ty + 8 * s;
        int ro = tj * 32 + ry, co = ti * 32 + tx;
        if (co > ro) {
            float v = su[tx][ry], h, l;
            split_tf32(v, h, l);
            Rh[(size_t)ro * DD + co] = h;
            Rl[(size_t)ro * DD + co] = l;
        }
    }
}

__global__ void abl_c2(const float* __restrict__ cent) {
    int n = blockIdx.x;
    __shared__ float sr[128];
    float s = 0.f;
    for (int j = threadIdx.x; j < DD; j += 128) {
        float v = cent[(size_t)n * DD + j];
        s += v * v;
    }
    sr[threadIdx.x] = s;
    __syncthreads();
    for (int k = 64; k > 0; k >>= 1) {
        if (threadIdx.x < k) sr[threadIdx.x] += sr[threadIdx.x + k];
        __syncthreads();
    }
    if (threadIdx.x == 0) g_c2[n] = sr[0];
}

__global__ __launch_bounds__(256) void abl_dot_nt(const float* __restrict__ A,
                                                  const float* __restrict__ Bm,
                                                  int Ma, int Nb, int which) {
    float* C = which ? g_dotood : g_dotin;
    __shared__ float sA[16][65];
    __shared__ float sB[16][65];
    int n0 = blockIdx.x * 64, m0 = blockIdx.y * 64;
    int t = threadIdx.x, tx = t & 15, ty = t >> 4;
    float acc[4][4];
#pragma unroll
    for (int r = 0; r < 4; r++)
#pragma unroll
        for (int c = 0; c < 4; c++) acc[r][c] = 0.f;

    for (int j0 = 0; j0 < DD; j0 += 16) {
#pragma unroll
        for (int e = 0; e < 4; e++) {
            int mm = (t >> 4) + 16 * e;
            int m = m0 + mm;
            sA[tx][mm] = (m < Ma) ? A[(size_t)m * DD + j0 + tx] : 0.f;
        }
#pragma unroll
        for (int e = 0; e < 4; e++) {
            int nn = (t >> 4) + 16 * e;
            int n = n0 + nn;
            sB[tx][nn] = (n < Nb) ? Bm[(size_t)n * DD + j0 + tx] : 0.f;
        }
        __syncthreads();
#pragma unroll
        for (int kk = 0; kk < 16; kk++) {
            float a[4], b[4];
#pragma unroll
            for (int r = 0; r < 4; r++) a[r] = sA[kk][ty * 4 + r];
#pragma unroll
            for (int c = 0; c < 4; c++) b[c] = sB[kk][tx * 4 + c];
#pragma unroll
            for (int r = 0; r < 4; r++)
#pragma unroll
                for (int c = 0; c < 4; c++) acc[r][c] += a[r] * b[c];
        }
        __syncthreads();
    }
#pragma unroll
    for (int r = 0; r < 4; r++) {
        int m = m0 + ty * 4 + r;
        if (m >= Ma) continue;
#pragma unroll
        for (int c = 0; c < 4; c++) {
            int n = n0 + tx * 4 + c;
            if (n < Nb) C[(size_t)m * Nb + n] = acc[r][c];
        }
    }
}

// fused: nearest class-k ball per ood sample + zero euc2 + pre-split B write
__global__ __launch_bounds__(256) void abl_near_bsplit(const float* __restrict__ ood,
                                                       const float* __restrict__ cent,
                                                       const float* __restrict__ delta,
                                                       int M, int N) {
    int k = blockIdx.x;
    int mb = blockIdx.y * 64;
    __shared__ int snb[64];
    int t = threadIdx.x;
    if (t < 64) {
        int m = mb + t;
        int mc = (m < M) ? m : (M - 1);
        int cnt = g_cnt[k];
        float best = 3.4e38f;
        int bi = 0;
        for (int i = 0; i < cnt; i++) {
            int n = g_clist[k * MAXN + i];
            float s = g_c2[n] - 2.f * g_dotood[(size_t)mc * N + n];
            if (s < best) { best = s; bi = n; }
        }
        snb[t] = bi;
        if (m < M) {
            g_dnear[k * M + m] = delta[bi];
            g_euc2ood[k * M + m] = 0.f;
        }
    }
    __syncthreads();
    float* bh = g_Bh + ((size_t)k * MAXM + mb) * DD;
    float* bl = g_Bl + ((size_t)k * MAXM + mb) * DD;
    const int C4 = DD / 4;   // 192
    for (int idx = t; idx < 64 * C4; idx += 256) {
        int row = idx / C4, c4 = idx % C4;
        int m = mb + row;
        int mc = (m < M) ? m : (M - 1);
        int nb = snb[row];
        float4 o = *(const float4*)(ood + (size_t)mc * DD + c4 * 4);
        float4 ce = *(const float4*)(cent + (size_t)nb * DD + c4 * 4);
        float4 v = make_float4(o.x - ce.x, o.y - ce.y, o.z - ce.z, o.w - ce.w);
        float4 h, l;
        split4(v, h, l);
        *(float4*)(bh + (size_t)row * DD + c4 * 4) = h;
        *(float4*)(bl + (size_t)row * DD + c4 * 4) = l;
    }
}

// ================= pipelined mma.sync tf32 GEMM (pre-split) ================
// D[128,128] tile of R_k @ Xdiff^T, 3xTF32: D += Ah.Bh + Al.Bh + Ah.Bl
// cp.async double-buffered k-chunks of 32.
#define KC   32
#define NCH  (DD / KC)          // 24
#define LDSW 36
#define TILE_F (128 * LDSW)     // 4608 floats per sub-tile
#define STAGE_F (4 * TILE_F)    // Ah,Al,Bh,Bl
#define SMEM_MMA_BYTES (2 * STAGE_F * 4)   // 147456

__global__ __launch_bounds__(256, 1) void abl_ood_mma2(int M) {
    extern __shared__ float dsm[];
    uint32_t sb = smem_to_u32(dsm);
    __shared__ float scol[128];

    int k = blockIdx.z;
    int rowBase = blockIdx.y * 128;
    int colBase = blockIdx.x * 128;

    const float* Ah = g_Rh + (size_t)k * DD * DD;
    const float* Al = g_Rl + (size_t)k * DD * DD;
    const float* Bh = g_Bh + ((size_t)k * MAXM + colBase) * DD;
    const float* Bl = g_Bl + ((size_t)k * MAXM + colBase) * DD;

    int t = threadIdx.x, wid = t >> 5, lane = t & 31;
    int wm = (wid >> 2) * 64;
    int wn = (wid & 3) * 32;
    int gid = lane >> 2, tig = lane & 3;

    if (t < 128) scol[t] = 0.f;

    float acc[4][4][4];
#pragma unroll
    for (int mt = 0; mt < 4; mt++)
#pragma unroll
        for (int nt = 0; nt < 4; nt++)
#pragma unroll
            for (int r = 0; r < 4; r++) acc[mt][nt][r] = 0.f;

    // ---- async chunk loader: 1024 16B segs per array, 4 arrays ----
    auto load_chunk = [&](int c, int s) {
        int j0 = c * KC;
        uint32_t base = sb + (uint32_t)(s * STAGE_F) * 4u;
#pragma unroll
        for (int e = 0; e < 4; e++) {
            int seg = t + 256 * e;
            int row = seg >> 3, c4 = seg & 7;
            uint32_t soff = (uint32_t)(row * LDSW + c4 * 4) * 4u;
            cp16(base + 0 * TILE_F * 4 + soff, Ah + (size_t)(rowBase + row) * DD + j0 + c4 * 4);
            cp16(base + 1 * TILE_F * 4 + soff, Al + (size_t)(rowBase + row) * DD + j0 + c4 * 4);
            cp16(base + 2 * TILE_F * 4 + soff, Bh + (size_t)row * DD + j0 + c4 * 4);
            cp16(base + 3 * TILE_F * 4 + soff, Bl + (size_t)row * DD + j0 + c4 * 4);
        }
    };

    load_chunk(0, 0);
    CP_COMMIT();

    for (int c = 0; c < NCH; c++) {
        int s = c & 1;
        if (c + 1 < NCH) {
            load_chunk(c + 1, s ^ 1);
            CP_COMMIT();
            CP_WAIT1();
        } else {
            CP_WAIT0();
        }
        __syncthreads();

        const float* sAh = dsm + s * STAGE_F;
        const float* sAl = sAh + TILE_F;
        const float* sBh = sAl + TILE_F;
        const float* sBl = sBh + TILE_F;

#pragma unroll
        for (int kt = 0; kt < 4; kt++) {
            int kb = kt * 8;
            uint32_t ah[4][4], al[4][4], bh[4][2], bl[4][2];
#pragma unroll
            for (int mt = 0; mt < 4; mt++) {
                int r0 = (wm + mt * 16 + gid) * LDSW + kb + tig;
                int r1 = r0 + 8 * LDSW;
                ah[mt][0] = __float_as_uint(sAh[r0]);
                ah[mt][1] = __float_as_uint(sAh[r1]);
                ah[mt][2] = __float_as_uint(sAh[r0 + 4]);
                ah[mt][3] = __float_as_uint(sAh[r1 + 4]);
                al[mt][0] = __float_as_uint(sAl[r0]);
                al[mt][1] = __float_as_uint(sAl[r1]);
                al[mt][2] = __float_as_uint(sAl[r0 + 4]);
                al[mt][3] = __float_as_uint(sAl[r1 + 4]);
            }
#pragma unroll
            for (int nt = 0; nt < 4; nt++) {
                int n0 = (wn + nt * 8 + gid) * LDSW + kb + tig;
                bh[nt][0] = __float_as_uint(sBh[n0]);
                bh[nt][1] = __float_as_uint(sBh[n0 + 4]);
                bl[nt][0] = __float_as_uint(sBl[n0]);
                bl[nt][1] = __float_as_uint(sBl[n0 + 4]);
            }
#pragma unroll
            for (int mt = 0; mt < 4; mt++)
#pragma unroll
                for (int nt = 0; nt < 4; nt++) {
                    mma_tf32(acc[mt][nt], ah[mt], bh[nt]);
                    mma_tf32(acc[mt][nt], al[mt], bh[nt]);
                    mma_tf32(acc[mt][nt], ah[mt], bl[nt]);
                }
        }
        __syncthreads();
    }

    // ---- epilogue: column sum of squares ----
#pragma unroll
    for (int nt = 0; nt < 4; nt++) {
        float s0 = 0.f, s1 = 0.f;
#pragma unroll
        for (int mt = 0; mt < 4; mt++) {
            s0 += acc[mt][nt][0] * acc[mt][nt][0] + acc[mt][nt][2] * acc[mt][nt][2];
            s1 += acc[mt][nt][1] * acc[mt][nt][1] + acc[mt][nt][3] * acc[mt][nt][3];
        }
#pragma unroll
        for (int o = 16; o >= 4; o >>= 1) {
            s0 += __shfl_down_sync(0xffffffffu, s0, o);
            s1 += __shfl_down_sync(0xffffffffu, s1, o);
        }
        if (lane < 4) {
            atomicAdd(&scol[wn + nt * 8 + 2 * lane], s0);
            atomicAdd(&scol[wn + nt * 8 + 2 * lane + 1], s1);
        }
    }
    __syncthreads();
    if (t < 128) {
        int col = colBase + t;
        if (col < M) atomicAdd(&g_euc2ood[k * M + col], scol[t]);
    }
}

// ======================= remaining kernels =================================
__global__ void abl_assign_in(const int* __restrict__ labels,
                              const float* __restrict__ delta, int B, int N) {
    int b = blockIdx.x * blockDim.x + threadIdx.x;
    if (b >= B) return;
    int lab = labels[b];
    int cnt = g_cnt[lab];
    float best = 3.4e38f;
    int bi = 0;
    for (int i = 0; i < cnt; i++) {
        int n = g_clist[lab * MAXN + i];
        float s = g_c2[n] - 2.f * g_dotin[(size_t)b * N + n];
        if (s < best) { best = s; bi = n; }
    }
    g_ballin[b] = bi;
    g_din[b] = delta[bi];
}

// in-dist matvec reads hi-only R (tf32-rounded; pos branch tolerance is loose)
__global__ void abl_indist(const float* __restrict__ pooled,
                           const float* __restrict__ cent,
                           const int* __restrict__ blab) {
    int b = blockIdx.x;
    __shared__ float sx[DD];
    __shared__ float swr[8];
    int bid = g_ballin[b];
    for (int j = threadIdx.x; j < DD; j += 256)
        sx[j] = pooled[(size_t)b * DD + j] - cent[(size_t)bid * DD + j];
    __syncthreads();
    int cls = blab[bid];
    const float* A = g_Rh + (size_t)cls * DD * DD;
    int w = threadIdx.x >> 5, lane = threadIdx.x & 31;
    float wsum = 0.f;
    for (int i = w; i < DD; i += 8) {
        const float4* row = reinterpret_cast<const float4*>(A + (size_t)i * DD);
        float p = 0.f;
        for (int j = lane; j < DD / 4; j += 32) {
            float4 r4 = row[j];
            p += r4.x * sx[4 * j] + r4.y * sx[4 * j + 1] +
                 r4.z * sx[4 * j + 2] + r4.w * sx[4 * j + 3];
        }
        for (int o = 16; o; o >>= 1) p += __shfl_down_sync(0xffffffffu, p, o);
        if (lane == 0) wsum += p * p;
    }
    if (lane == 0) swr[w] = wsum;
    __syncthreads();
    if (threadIdx.x == 0) {
        float s = 0.f;
        for (int i = 0; i < 8; i++) s += swr[i];
        g_eucin2[b] = s;
    }
}

__global__ void abl_finalize(float* __restrict__ out, int B, int M, int K, int out_size) {
    __shared__ float sred[256];
    int t = threadIdx.x;

    float pl = 0.f, pn = 0.f, nn = 0.f;
    for (int b = t; b < B; b += 256) {
        float e = sqrtf(g_eucin2[b]);
        float d = g_din[b];
        pl += (d > e) ? expf(e - d) : (e - d);
        if (e > d) pn += 1.f;
        if (e < d) nn += 1.f;
    }
    float ns = 0.f;
    for (int m = t; m < M; m += 256) {
        float s = 0.f;
        for (int k = 0; k < K; k++) {
            float e = sqrtf(g_euc2ood[k * M + m]);
            float d = g_dnear[k * M + m];
            s += (d > e) ? (d - e + BETA_C) : BETA_C * expf(d - e);
        }
        ns += s;
    }

    float vals[4] = {pl, pn, nn, ns};
    float red[4];
    for (int v = 0; v < 4; v++) {
        sred[t] = vals[v];
        __syncthreads();
        for (int s2 = 128; s2 > 0; s2 >>= 1) {
            if (t < s2) sred[t] += sred[t + s2];
            __syncthreads();
        }
        red[v] = sred[0];
        __syncthreads();
    }
    if (t == 0) {
        float pos_mean = red[0] / (float)B;
        float neg_mean = red[3] / (float)M;
        if (out_size > 0) out[0] = pos_mean;
        if (out_size > 1) out[1] = neg_mean;
        if (out_size > 2) out[2] = red[1];
        if (out_size > 3) out[3] = red[2];
        if (out_size > 4) out[4] = pos_mean + neg_mean;
    }
}

// ---------------------------------------------------------------------------
extern "C" void kernel_launch(void* const* d_in, const int* in_sizes, int n_in,
                              void* d_out, int out_size) {
    const float* pooled = (const float*)d_in[0];
    const float* ood    = (const float*)d_in[1];
    const float* cent   = (const float*)d_in[2];
    const float* delta  = (const float*)d_in[3];
    const float* L      = (const float*)d_in[4];
    const float* U      = (const float*)d_in[5];
    const float* Ddm    = (const float*)d_in[6];
    const int*   labels = (const int*)d_in[7];
    const int*   blab   = (const int*)d_in[8];

    int B = in_sizes[0] / DD;
    int M = in_sizes[1] / DD;
    int N = in_sizes[3];
    int K = in_sizes[6] / DD;
    int NTRI = in_sizes[4] / K;

    if (B > MAXB) B = MAXB;
    if (M > MAXM) M = MAXM;
    if (N > MAXN) N = MAXN;
    if (K > MAXK) K = MAXK;

    int ntiles = (DD / 32) * (DD / 32 + 1) / 2;   // 300

    cudaFuncSetAttribute(abl_ood_mma2, cudaFuncAttributeMaxDynamicSharedMemorySize,
                         SMEM_MMA_BYTES);

    // order chosen so the big GEMM is the 6th launch (ncu -s 5 -c 1 profiles it)
    abl_clist_all<<<1, 256>>>(blab, N, K);                                        // 1
    abl_build_Rsplit<<<dim3(ntiles, K), 256>>>(L, U, Ddm, NTRI);                  // 2
    abl_c2<<<N, 128>>>(cent);                                                     // 3
    abl_dot_nt<<<dim3((N + 63) / 64, (M + 63) / 64), 256>>>(ood, cent, M, N, 1);  // 4
    abl_near_bsplit<<<dim3(K, (M + 63) / 64), 256>>>(ood, cent, delta, M, N);     // 5
    abl_ood_mma2<<<dim3((M + 127) / 128, DD / 128, K), 256, SMEM_MMA_BYTES>>>(M); // 6 <- profiled
    abl_dot_nt<<<dim3((N + 63) / 64, (B + 63) / 64), 256>>>(pooled, cent, B, N, 0); // 7
    abl_assign_in<<<(B + 255) / 256, 256>>>(labels, delta, B, N);                 // 8
    abl_indist<<<B, 256>>>(pooled, cent, blab);                                   // 9
    abl_finalize<<<1, 256>>>((float*)d_out, B, M, K, out_size);                   // 10
}

// round 11
// speedup vs baseline: 1.0311x; 1.0311x over previous
#include <cuda_runtime.h>
#include <math.h>
#include <stdint.h>

#define DD   768
#define MAXK 150
#define MAXN 1500
#define MAXB 256
#define MAXM 256
#define BETA_C 0.1f

// ---- scratch (static device globals; no allocation) ----
__device__ float g_S[(size_t)MAXK * DD * DD];    // tf32-rounded S = R - I
__device__ float g_B[(size_t)MAXK * MAXM * DD];  // fp32 x = ood - c_near per (k,m)
__device__ float g_c2[MAXN];
__device__ float g_dotin[MAXB * MAXN];
__device__ float g_dotood[MAXM * MAXN];
__device__ int   g_cnt[MAXK];
__device__ int   g_clist[MAXK * MAXN];
__device__ int   g_ballin[MAXB];
__device__ float g_din[MAXB];
__device__ float g_dnear[MAXK * MAXM];
__device__ float g_x2[MAXK * MAXM];              // ||x||^2 exact fp32
__device__ float g_xy[MAXK * MAXM];              // x . y   (accumulated)
__device__ float g_y2[MAXK * MAXM];              // ||y||^2 (accumulated)
__device__ float g_eucin2[MAXB];

// ======================= helpers ===========================================
__device__ __forceinline__ uint32_t tf32_of(float x) {
    uint32_t h;
    asm("cvt.rna.tf32.f32 %0, %1;" : "=r"(h) : "f"(x));
    return h;
}
__device__ __forceinline__ float tf32r(float x) {
    return __uint_as_float(tf32_of(x));
}
__device__ __forceinline__ void mma_tf32(float* d, const uint32_t* a, const uint32_t* b) {
    asm volatile(
        "mma.sync.aligned.m16n8k8.row.col.f32.tf32.tf32.f32 "
        "{%0,%1,%2,%3}, {%4,%5,%6,%7}, {%8,%9}, {%0,%1,%2,%3};"
        : "+f"(d[0]), "+f"(d[1]), "+f"(d[2]), "+f"(d[3])
        : "r"(a[0]), "r"(a[1]), "r"(a[2]), "r"(a[3]), "r"(b[0]), "r"(b[1]));
}

// ======================= setup kernels =====================================
__global__ void abl_clist_all(const int* __restrict__ blab, int N, int K) {
    int t = threadIdx.x;
    for (int i = t; i < K; i += 256) g_cnt[i] = 0;
    __syncthreads();
    for (int n = t; n < N; n += 256) {
        int kk = blab[n];
        int pos = atomicAdd(&g_cnt[kk], 1);
        g_clist[kk * MAXN + pos] = n;
    }
}

// build tf32-rounded S = R - I from packed L/U/Dd
__global__ void abl_build_S(const float* __restrict__ L, const float* __restrict__ U,
                            const float* __restrict__ Ddm, int NTRI) {
    int k = blockIdx.y;
    int tidx = blockIdx.x;
    int ti = 0;
    while ((ti + 1) * (ti + 2) / 2 <= tidx) ti++;
    int tj = tidx - ti * (ti + 1) / 2;

    const float* Lk = L + (size_t)k * NTRI;
    const float* Uk = U + (size_t)k * NTRI;
    float* Sk = g_S + (size_t)k * DD * DD;

    __shared__ float su[32][33];
    int tx = threadIdx.x & 31, ty = threadIdx.x >> 5;
#pragma unroll
    for (int s = 0; s < 4; s++) {
        int ry = ty + 8 * s;
        int r = ti * 32 + ry, c = tj * 32 + tx;
        if (r > c) {
            size_t p = (size_t)r * (r - 1) / 2 + c;
            Sk[(size_t)r * DD + c] = tf32r(Lk[p]);
            su[ry][tx] = Uk[p];
        } else if (r == c) {
            Sk[(size_t)r * DD + c] = tf32r(Ddm[(size_t)k * DD + r] - 1.0f);
        }
    }
    __syncthreads();
#pragma unroll
    for (int s = 0; s < 4; s++) {
        int ry = ty + 8 * s;
        int ro = tj * 32 + ry, co = ti * 32 + tx;
        if (co > ro) Sk[(size_t)ro * DD + co] = tf32r(su[tx][ry]);
    }
}

__global__ void abl_c2(const float* __restrict__ cent) {
    int n = blockIdx.x;
    __shared__ float sr[128];
    float s = 0.f;
    for (int j = threadIdx.x; j < DD; j += 128) {
        float v = cent[(size_t)n * DD + j];
        s += v * v;
    }
    sr[threadIdx.x] = s;
    __syncthreads();
    for (int k = 64; k > 0; k >>= 1) {
        if (threadIdx.x < k) sr[threadIdx.x] += sr[threadIdx.x + k];
        __syncthreads();
    }
    if (threadIdx.x == 0) g_c2[n] = sr[0];
}

__global__ __launch_bounds__(256) void abl_dot_nt(const float* __restrict__ A,
                                                  const float* __restrict__ Bm,
                                                  int Ma, int Nb, int which) {
    float* C = which ? g_dotood : g_dotin;
    __shared__ float sA[16][65];
    __shared__ float sB[16][65];
    int n0 = blockIdx.x * 64, m0 = blockIdx.y * 64;
    int t = threadIdx.x, tx = t & 15, ty = t >> 4;
    float acc[4][4];
#pragma unroll
    for (int r = 0; r < 4; r++)
#pragma unroll
        for (int c = 0; c < 4; c++) acc[r][c] = 0.f;

    for (int j0 = 0; j0 < DD; j0 += 16) {
#pragma unroll
        for (int e = 0; e < 4; e++) {
            int mm = (t >> 4) + 16 * e;
            int m = m0 + mm;
            sA[tx][mm] = (m < Ma) ? A[(size_t)m * DD + j0 + tx] : 0.f;
        }
#pragma unroll
        for (int e = 0; e < 4; e++) {
            int nn = (t >> 4) + 16 * e;
            int n = n0 + nn;
            sB[tx][nn] = (n < Nb) ? Bm[(size_t)n * DD + j0 + tx] : 0.f;
        }
        __syncthreads();
#pragma unroll
        for (int kk = 0; kk < 16; kk++) {
            float a[4], b[4];
#pragma unroll
            for (int r = 0; r < 4; r++) a[r] = sA[kk][ty * 4 + r];
#pragma unroll
            for (int c = 0; c < 4; c++) b[c] = sB[kk][tx * 4 + c];
#pragma unroll
            for (int r = 0; r < 4; r++)
#pragma unroll
                for (int c = 0; c < 4; c++) acc[r][c] += a[r] * b[c];
        }
        __syncthreads();
    }
#pragma unroll
    for (int r = 0; r < 4; r++) {
        int m = m0 + ty * 4 + r;
        if (m >= Ma) continue;
#pragma unroll
        for (int c = 0; c < 4; c++) {
            int n = n0 + tx * 4 + c;
            if (n < Nb) C[(size_t)m * Nb + n] = acc[r][c];
        }
    }
}

// fused: nearest class-k ball, dnear, x = diff (fp32), ||x||^2, zero xy/y2
__global__ __launch_bounds__(256) void abl_near_b(const float* __restrict__ ood,
                                                  const float* __restrict__ cent,
                                                  const float* __restrict__ delta,
                                                  int M, int N) {
    int k = blockIdx.x;
    int mb = blockIdx.y * 64;
    __shared__ int snb[64];
    int t = threadIdx.x;
    if (t < 64) {
        int m = mb + t;
        int mc = (m < M) ? m : (M - 1);
        int cnt = g_cnt[k];
        float best = 3.4e38f;
        int bi = 0;
        for (int i = 0; i < cnt; i++) {
            int n = g_clist[k * MAXN + i];
            float s = g_c2[n] - 2.f * g_dotood[(size_t)mc * N + n];
            if (s < best) { best = s; bi = n; }
        }
        snb[t] = bi;
        if (m < M) {
            g_dnear[k * M + m] = delta[bi];
            g_xy[k * M + m] = 0.f;
            g_y2[k * M + m] = 0.f;
        }
    }
    __syncthreads();
    int row = t >> 2, quad = t & 3;
    int m = mb + row;
    int mc = (m < M) ? m : (M - 1);
    int nb = snb[row];
    float* bo = g_B + ((size_t)k * MAXM + mb + row) * DD;
    float sum2 = 0.f;
    for (int c4 = quad; c4 < DD / 4; c4 += 4) {
        float4 o = *(const float4*)(ood + (size_t)mc * DD + c4 * 4);
        float4 ce = *(const float4*)(cent + (size_t)nb * DD + c4 * 4);
        float4 v = make_float4(o.x - ce.x, o.y - ce.y, o.z - ce.z, o.w - ce.w);
        *(float4*)(bo + c4 * 4) = v;
        sum2 += v.x * v.x + v.y * v.y + v.z * v.z + v.w * v.w;
    }
    sum2 += __shfl_down_sync(0xffffffffu, sum2, 2, 4);
    sum2 += __shfl_down_sync(0xffffffffu, sum2, 1, 4);
    if (quad == 0 && m < M) g_x2[k * M + m] = sum2;
}

// ================= single-pass tf32 GEMM: y = S_k . x^T ====================
// D[128,128] tile; epilogue accumulates per-column sum(y^2) and sum(x*y).
#define KC   32
#define NCH  (DD / KC)          // 24
#define LDSW 36
#define TILE_F (128 * LDSW)

__global__ __launch_bounds__(256, 2) void abl_ood_s(int M) {
    __shared__ float sA[TILE_F];
    __shared__ float sB[TILE_F];
    __shared__ float scY[128];
    __shared__ float scX[128];

    int k = blockIdx.z;
    int rowBase = blockIdx.y * 128;
    int colBase = blockIdx.x * 128;

    const float* A = g_S + (size_t)k * DD * DD;
    const float* Bp = g_B + ((size_t)k * MAXM + colBase) * DD;

    int t = threadIdx.x, wid = t >> 5, lane = t & 31;
    int wm = (wid >> 2) * 64;
    int wn = (wid & 3) * 32;
    int gid = lane >> 2, tig = lane & 3;

    if (t < 128) { scY[t] = 0.f; scX[t] = 0.f; }

    float acc[4][4][4];
#pragma unroll
    for (int mt = 0; mt < 4; mt++)
#pragma unroll
        for (int nt = 0; nt < 4; nt++)
#pragma unroll
            for (int r = 0; r < 4; r++) acc[mt][nt][r] = 0.f;

    for (int c = 0; c < NCH; c++) {
        int j0 = c * KC;
        // A tile: pre-rounded tf32, straight copy
#pragma unroll
        for (int e = 0; e < 4; e++) {
            int idx = t + 256 * e;
            int row = idx >> 3, c4 = idx & 7;
            *(float4*)&sA[row * LDSW + c4 * 4] =
                *(const float4*)(A + (size_t)(rowBase + row) * DD + j0 + c4 * 4);
        }
        // B tile: fp32 -> tf32 round on store
#pragma unroll
        for (int e = 0; e < 4; e++) {
            int idx = t + 256 * e;
            int row = idx >> 3, c4 = idx & 7;
            float4 v = *(const float4*)(Bp + (size_t)row * DD + j0 + c4 * 4);
            v.x = tf32r(v.x); v.y = tf32r(v.y); v.z = tf32r(v.z); v.w = tf32r(v.w);
            *(float4*)&sB[row * LDSW + c4 * 4] = v;
        }
        __syncthreads();

#pragma unroll
        for (int kt = 0; kt < 4; kt++) {
            int kb = kt * 8;
            uint32_t ah[4][4], bh[4][2];
#pragma unroll
            for (int mt = 0; mt < 4; mt++) {
                int r0 = (wm + mt * 16 + gid) * LDSW + kb + tig;
                int r1 = r0 + 8 * LDSW;
                ah[mt][0] = __float_as_uint(sA[r0]);
                ah[mt][1] = __float_as_uint(sA[r1]);
                ah[mt][2] = __float_as_uint(sA[r0 + 4]);
                ah[mt][3] = __float_as_uint(sA[r1 + 4]);
            }
#pragma unroll
            for (int nt = 0; nt < 4; nt++) {
                int n0 = (wn + nt * 8 + gid) * LDSW + kb + tig;
                bh[nt][0] = __float_as_uint(sB[n0]);
                bh[nt][1] = __float_as_uint(sB[n0 + 4]);
            }
#pragma unroll
            for (int mt = 0; mt < 4; mt++)
#pragma unroll
                for (int nt = 0; nt < 4; nt++)
                    mma_tf32(acc[mt][nt], ah[mt], bh[nt]);
        }
        __syncthreads();
    }

    // ---- epilogue: per-column sum(y^2) and sum(x*y) ----
    // acc[mt][nt][r]: row = wm+16mt+gid+(r>=2?8:0), col = wn+8nt+2tig+(r&1)
#pragma unroll
    for (int nt = 0; nt < 4; nt++) {
        int col0 = wn + nt * 8 + 2 * tig;
        float y0 = 0.f, y1 = 0.f, x0 = 0.f, x1 = 0.f;
#pragma unroll
        for (int mt = 0; mt < 4; mt++) {
            int r0g = rowBase + wm + 16 * mt + gid;
            float xa0 = Bp[(size_t)col0 * DD + r0g];
            float xa2 = Bp[(size_t)col0 * DD + r0g + 8];
            float xb1 = Bp[(size_t)(col0 + 1) * DD + r0g];
            float xb3 = Bp[(size_t)(col0 + 1) * DD + r0g + 8];
            float a0 = acc[mt][nt][0], a1 = acc[mt][nt][1];
            float a2 = acc[mt][nt][2], a3 = acc[mt][nt][3];
            y0 += a0 * a0 + a2 * a2;
            y1 += a1 * a1 + a3 * a3;
            x0 += a0 * xa0 + a2 * xa2;
            x1 += a1 * xb1 + a3 * xb3;
        }
#pragma unroll
        for (int o = 16; o >= 4; o >>= 1) {
            y0 += __shfl_down_sync(0xffffffffu, y0, o);
            y1 += __shfl_down_sync(0xffffffffu, y1, o);
            x0 += __shfl_down_sync(0xffffffffu, x0, o);
            x1 += __shfl_down_sync(0xffffffffu, x1, o);
        }
        if (lane < 4) {
            atomicAdd(&scY[wn + nt * 8 + 2 * lane], y0);
            atomicAdd(&scY[wn + nt * 8 + 2 * lane + 1], y1);
            atomicAdd(&scX[wn + nt * 8 + 2 * lane], x0);
            atomicAdd(&scX[wn + nt * 8 + 2 * lane + 1], x1);
        }
    }
    __syncthreads();
    if (t < 128) {
        int col = colBase + t;
        if (col < M) {
            atomicAdd(&g_y2[k * M + col], scY[t]);
            atomicAdd(&g_xy[k * M + col], scX[t]);
        }
    }
}

// ======================= remaining kernels =================================
__global__ void abl_assign_in(const int* __restrict__ labels,
                              const float* __restrict__ delta, int B, int N) {
    int b = blockIdx.x * blockDim.x + threadIdx.x;
    if (b >= B) return;
    int lab = labels[b];
    int cnt = g_cnt[lab];
    float best = 3.4e38f;
    int bi = 0;
    for (int i = 0; i < cnt; i++) {
        int n = g_clist[lab * MAXN + i];
        float s = g_c2[n] - 2.f * g_dotin[(size_t)b * N + n];
        if (s < best) { best = s; bi = n; }
    }
    g_ballin[b] = bi;
    g_din[b] = delta[bi];
}

// in-dist: ||x + S x||^2 per sample (one block per sample)
__global__ void abl_indist(const float* __restrict__ pooled,
                           const float* __restrict__ cent,
                           const int* __restrict__ blab) {
    int b = blockIdx.x;
    __shared__ float sx[DD];
    __shared__ float swr[8];
    int bid = g_ballin[b];
    for (int j = threadIdx.x; j < DD; j += 256)
        sx[j] = pooled[(size_t)b * DD + j] - cent[(size_t)bid * DD + j];
    __syncthreads();
    int cls = blab[bid];
    const float* A = g_S + (size_t)cls * DD * DD;
    int w = threadIdx.x >> 5, lane = threadIdx.x & 31;
    float wsum = 0.f;
    for (int i = w; i < DD; i += 8) {
        const float4* row = reinterpret_cast<const float4*>(A + (size_t)i * DD);
        float p = 0.f;
        for (int j = lane; j < DD / 4; j += 32) {
            float4 r4 = row[j];
            p += r4.x * sx[4 * j] + r4.y * sx[4 * j + 1] +
                 r4.z * sx[4 * j + 2] + r4.w * sx[4 * j + 3];
        }
        for (int o = 16; o; o >>= 1) p += __shfl_down_sync(0xffffffffu, p, o);
        if (lane == 0) {
            float z = sx[i] + p;   // (x + Sx)_i
            wsum += z * z;
        }
    }
    if (lane == 0) swr[w] = wsum;
    __syncthreads();
    if (threadIdx.x == 0) {
        float s = 0.f;
        for (int i = 0; i < 8; i++) s += swr[i];
        g_eucin2[b] = s;
    }
}

__global__ void abl_finalize(float* __restrict__ out, int B, int M, int K, int out_size) {
    __shared__ float sred[256];
    int t = threadIdx.x;

    float pl = 0.f, pn = 0.f, nn = 0.f;
    for (int b = t; b < B; b += 256) {
        float e = sqrtf(g_eucin2[b]);
        float d = g_din[b];
        pl += (d > e) ? expf(e - d) : (e - d);
        if (e > d) pn += 1.f;
        if (e < d) nn += 1.f;
    }
    float ns = 0.f;
    for (int m = t; m < M; m += 256) {
        float s = 0.f;
        for (int k = 0; k < K; k++) {
            float e2 = g_x2[k * M + m] + 2.f * g_xy[k * M + m] + g_y2[k * M + m];
            float e = sqrtf(fmaxf(e2, 0.f));
            float d = g_dnear[k * M + m];
            s += (d > e) ? (d - e + BETA_C) : BETA_C * expf(d - e);
        }
        ns += s;
    }

    float vals[4] = {pl, pn, nn, ns};
    float red[4];
    for (int v = 0; v < 4; v++) {
        sred[t] = vals[v];
        __syncthreads();
        for (int s2 = 128; s2 > 0; s2 >>= 1) {
            if (t < s2) sred[t] += sred[t + s2];
            __syncthreads();
        }
        red[v] = sred[0];
        __syncthreads();
    }
    if (t == 0) {
        float pos_mean = red[0] / (float)B;
        float neg_mean = red[3] / (float)M;
        if (out_size > 0) out[0] = pos_mean;
        if (out_size > 1) out[1] = neg_mean;
        if (out_size > 2) out[2] = red[1];
        if (out_size > 3) out[3] = red[2];
        if (out_size > 4) out[4] = pos_mean + neg_mean;
    }
}

// ---------------------------------------------------------------------------
extern "C" void kernel_launch(void* const* d_in, const int* in_sizes, int n_in,
                              void* d_out, int out_size) {
    const float* pooled = (const float*)d_in[0];
    const float* ood    = (const float*)d_in[1];
    const float* cent   = (const float*)d_in[2];
    const float* delta  = (const float*)d_in[3];
    const float* L      = (const float*)d_in[4];
    const float* U      = (const float*)d_in[5];
    const float* Ddm    = (const float*)d_in[6];
    const int*   labels = (const int*)d_in[7];
    const int*   blab   = (const int*)d_in[8];

    int B = in_sizes[0] / DD;
    int M = in_sizes[1] / DD;
    int N = in_sizes[3];
    int K = in_sizes[6] / DD;
    int NTRI = in_sizes[4] / K;

    if (B > MAXB) B = MAXB;
    if (M > MAXM) M = MAXM;
    if (N > MAXN) N = MAXN;
    if (K > MAXK) K = MAXK;

    int ntiles = (DD / 32) * (DD / 32 + 1) / 2;   // 300

    abl_clist_all<<<1, 256>>>(blab, N, K);                                          // 1
    abl_build_S<<<dim3(ntiles, K), 256>>>(L, U, Ddm, NTRI);                         // 2
    abl_c2<<<N, 128>>>(cent);                                                       // 3
    abl_dot_nt<<<dim3((N + 63) / 64, (M + 63) / 64), 256>>>(ood, cent, M, N, 1);    // 4
    abl_near_b<<<dim3(K, (M + 63) / 64), 256>>>(ood, cent, delta, M, N);            // 5
    abl_ood_s<<<dim3((M + 127) / 128, DD / 128, K), 256>>>(M);                      // 6
    abl_dot_nt<<<dim3((N + 63) / 64, (B + 63) / 64), 256>>>(pooled, cent, B, N, 0); // 7
    abl_assign_in<<<(B + 255) / 256, 256>>>(labels, delta, B, N);                   // 8
    abl_indist<<<B, 256>>>(pooled, cent, blab);                                     // 9
    abl_finalize<<<1, 256>>>((float*)d_out, B, M, K, out_size);                     // 10
}

// round 12
// speedup vs baseline: 1.7813x; 1.7275x over previous
#include <cuda_runtime.h>
#include <math.h>
#include <stdint.h>

#define DD   768
#define MAXK 150
#define MAXN 1500
#define MAXB 256
#define MAXM 256
#define BETA_C 0.1f

// ---- scratch (static device globals; no allocation) ----
__device__ float g_S[(size_t)MAXK * DD * DD];    // tf32-rounded S = R - I
__device__ float g_B[(size_t)MAXK * MAXM * DD];  // tf32-rounded x = ood - c_near
__device__ float g_c2[MAXN];
__device__ float g_dotin[MAXB * MAXN];
__device__ float g_dotood[MAXM * MAXN];
__device__ int   g_cnt[MAXK];
__device__ int   g_clist[MAXK * MAXN];
__device__ int   g_scnt[MAXK];                   // in-dist samples per class
__device__ int   g_slist[MAXK * MAXB];
__device__ int   g_ballin[MAXB];
__device__ float g_din[MAXB];
__device__ float g_dnear[MAXK * MAXM];
__device__ float g_x2[MAXK * MAXM];              // ||x||^2 exact fp32
__device__ float g_xy[MAXK * MAXM];
__device__ float g_y2[MAXK * MAXM];
__device__ float g_eucin2[MAXB];

// ======================= helpers ===========================================
__device__ __forceinline__ uint32_t tf32_of(float x) {
    uint32_t h;
    asm("cvt.rna.tf32.f32 %0, %1;" : "=r"(h) : "f"(x));
    return h;
}
__device__ __forceinline__ float tf32r(float x) {
    return __uint_as_float(tf32_of(x));
}
__device__ __forceinline__ void mma_tf32(float* d, const uint32_t* a, const uint32_t* b) {
    asm volatile(
        "mma.sync.aligned.m16n8k8.row.col.f32.tf32.tf32.f32 "
        "{%0,%1,%2,%3}, {%4,%5,%6,%7}, {%8,%9}, {%0,%1,%2,%3};"
        : "+f"(d[0]), "+f"(d[1]), "+f"(d[2]), "+f"(d[3])
        : "r"(a[0]), "r"(a[1]), "r"(a[2]), "r"(a[3]), "r"(b[0]), "r"(b[1]));
}

// ======================= setup kernels =====================================
// class->ball lists, class->sample lists, zero eucin2
__global__ void abl_clist_all(const int* __restrict__ blab,
                              const int* __restrict__ labels, int N, int K, int B) {
    int t = threadIdx.x;
    for (int i = t; i < K; i += 256) { g_cnt[i] = 0; g_scnt[i] = 0; }
    __syncthreads();
    for (int n = t; n < N; n += 256) {
        int kk = blab[n];
        int pos = atomicAdd(&g_cnt[kk], 1);
        g_clist[kk * MAXN + pos] = n;
    }
    for (int b = t; b < B; b += 256) {
        int kk = labels[b];
        int pos = atomicAdd(&g_scnt[kk], 1);
        g_slist[kk * MAXB + pos] = b;
        g_eucin2[b] = 0.f;
    }
}

// blocks [0,Nc): centroid sumsq; blocks [Nc, Nc+zb): zero dot buffers
__global__ void abl_c2zero(const float* __restrict__ cent, int Nc, int totf) {
    int bid = blockIdx.x;
    if (bid < Nc) {
        __shared__ float sr[128];
        float s = 0.f;
        for (int j = threadIdx.x; j < DD; j += 128) {
            float v = cent[(size_t)bid * DD + j];
            s += v * v;
        }
        sr[threadIdx.x] = s;
        __syncthreads();
        for (int k = 64; k > 0; k >>= 1) {
            if (threadIdx.x < k) sr[threadIdx.x] += sr[threadIdx.x + k];
            __syncthreads();
        }
        if (threadIdx.x == 0) g_c2[bid] = sr[0];
    } else {
        int base = (bid - Nc) * 512 + threadIdx.x;   // 128 threads used x4
#pragma unroll
        for (int r = 0; r < 4; r++) {
            int i = base + r * 128;
            if (i < totf) {
                int half = totf / 2;
                if (i < half) g_dotin[i] = 0.f;
                else g_dotood[i - half] = 0.f;
            }
        }
    }
}

// build tf32-rounded S = R - I from packed L/U/Dd
__global__ void abl_build_S(const float* __restrict__ L, const float* __restrict__ U,
                            const float* __restrict__ Ddm, int NTRI) {
    int k = blockIdx.y;
    int tidx = blockIdx.x;
    int ti = 0;
    while ((ti + 1) * (ti + 2) / 2 <= tidx) ti++;
    int tj = tidx - ti * (ti + 1) / 2;

    const float* Lk = L + (size_t)k * NTRI;
    const float* Uk = U + (size_t)k * NTRI;
    float* Sk = g_S + (size_t)k * DD * DD;

    __shared__ float su[32][33];
    int tx = threadIdx.x & 31, ty = threadIdx.x >> 5;
#pragma unroll
    for (int s = 0; s < 4; s++) {
        int ry = ty + 8 * s;
        int r = ti * 32 + ry, c = tj * 32 + tx;
        if (r > c) {
            size_t p = (size_t)r * (r - 1) / 2 + c;
            Sk[(size_t)r * DD + c] = tf32r(Lk[p]);
            su[ry][tx] = Uk[p];
        } else if (r == c) {
            Sk[(size_t)r * DD + c] = tf32r(Ddm[(size_t)k * DD + r] - 1.0f);
        }
    }
    __syncthreads();
#pragma unroll
    for (int s = 0; s < 4; s++) {
        int ry = ty + 8 * s;
        int ro = tj * 32 + ry, co = ti * 32 + tx;
        if (co > ro) Sk[(size_t)ro * DD + co] = tf32r(su[tx][ry]);
    }
}

// ---- combined dot kernel: rows [0,B) pooled -> g_dotin, [B,B+M) ood -> g_dotood
// k-split over blockIdx.z (4 slices of 192), atomicAdd into zeroed C.
__global__ __launch_bounds__(256) void abl_dot_comb(const float* __restrict__ pooled,
                                                    const float* __restrict__ ood,
                                                    const float* __restrict__ cent,
                                                    int B, int M, int N) {
    __shared__ float sA[16][65];
    __shared__ float sB[16][65];
    int n0 = blockIdx.x * 64;
    int rows0 = blockIdx.y * 64;
    int isood = (rows0 >= B);
    const float* src = isood ? ood : pooled;
    int rbase = isood ? (rows0 - B) : rows0;
    int rcount = isood ? M : B;
    float* C = isood ? g_dotood : g_dotin;

    int ks0 = blockIdx.z * (DD / 4);
    int t = threadIdx.x, tx = t & 15, ty = t >> 4;
    float acc[4][4];
#pragma unroll
    for (int r = 0; r < 4; r++)
#pragma unroll
        for (int c = 0; c < 4; c++) acc[r][c] = 0.f;

    for (int j0 = ks0; j0 < ks0 + DD / 4; j0 += 16) {
#pragma unroll
        for (int e = 0; e < 4; e++) {
            int mm = ty + 16 * e;
            int m = rbase + mm;
            sA[tx][mm] = (m < rcount) ? src[(size_t)m * DD + j0 + tx] : 0.f;
        }
#pragma unroll
        for (int e = 0; e < 4; e++) {
            int nn = ty + 16 * e;
            int n = n0 + nn;
            sB[tx][nn] = (n < N) ? cent[(size_t)n * DD + j0 + tx] : 0.f;
        }
        __syncthreads();
#pragma unroll
        for (int kk = 0; kk < 16; kk++) {
            float a[4], b[4];
#pragma unroll
            for (int r = 0; r < 4; r++) a[r] = sA[kk][ty * 4 + r];
#pragma unroll
            for (int c = 0; c < 4; c++) b[c] = sB[kk][tx * 4 + c];
#pragma unroll
            for (int r = 0; r < 4; r++)
#pragma unroll
                for (int c = 0; c < 4; c++) acc[r][c] += a[r] * b[c];
        }
        __syncthreads();
    }
#pragma unroll
    for (int r = 0; r < 4; r++) {
        int m = rbase + ty * 4 + r;
        if (m >= rcount) continue;
#pragma unroll
        for (int c = 0; c < 4; c++) {
            int n = n0 + tx * 4 + c;
            if (n < N) atomicAdd(&C[(size_t)m * N + n], acc[r][c]);
        }
    }
}

// fused: nearest class-k ball, dnear, x (tf32-rounded store, exact x2), zero xy/y2
__global__ __launch_bounds__(256) void abl_near_b(const float* __restrict__ ood,
                                                  const float* __restrict__ cent,
                                                  const float* __restrict__ delta,
                                                  int M, int N) {
    int k = blockIdx.x;
    int mb = blockIdx.y * 64;
    __shared__ int snb[64];
    int t = threadIdx.x;
    if (t < 64) {
        int m = mb + t;
        int mc = (m < M) ? m : (M - 1);
        int cnt = g_cnt[k];
        float best = 3.4e38f;
        int bi = 0;
        for (int i = 0; i < cnt; i++) {
            int n = g_clist[k * MAXN + i];
            float s = g_c2[n] - 2.f * g_dotood[(size_t)mc * N + n];
            if (s < best) { best = s; bi = n; }
        }
        snb[t] = bi;
        if (m < M) {
            g_dnear[k * M + m] = delta[bi];
            g_xy[k * M + m] = 0.f;
            g_y2[k * M + m] = 0.f;
        }
    }
    __syncthreads();
    int row = t >> 2, quad = t & 3;
    int m = mb + row;
    int mc = (m < M) ? m : (M - 1);
    int nb = snb[row];
    float* bo = g_B + ((size_t)k * MAXM + mb + row) * DD;
    float sum2 = 0.f;
    for (int c4 = quad; c4 < DD / 4; c4 += 4) {
        float4 o = *(const float4*)(ood + (size_t)mc * DD + c4 * 4);
        float4 ce = *(const float4*)(cent + (size_t)nb * DD + c4 * 4);
        float4 v = make_float4(o.x - ce.x, o.y - ce.y, o.z - ce.z, o.w - ce.w);
        sum2 += v.x * v.x + v.y * v.y + v.z * v.z + v.w * v.w;   // exact
        v.x = tf32r(v.x); v.y = tf32r(v.y); v.z = tf32r(v.z); v.w = tf32r(v.w);
        *(float4*)(bo + c4 * 4) = v;
    }
    sum2 += __shfl_down_sync(0xffffffffu, sum2, 2, 4);
    sum2 += __shfl_down_sync(0xffffffffu, sum2, 1, 4);
    if (quad == 0 && m < M) g_x2[k * M + m] = sum2;
}

// ================= single-pass tf32 GEMM: y = S_k . x^T ====================
#define KC   32
#define NCH  (DD / KC)          // 24
#define LDSW 36
#define TILE_F (128 * LDSW)
#define LDX  132                // x-slice smem stride

__global__ __launch_bounds__(256, 2) void abl_ood_s2(int M) {
    __shared__ float sbuf[2 * TILE_F];
    __shared__ float scY[128];
    __shared__ float scX[128];
    float* sA = sbuf;
    float* sB = sbuf + TILE_F;

    int k = blockIdx.z;
    int rowBase = blockIdx.y * 128;
    int colBase = blockIdx.x * 128;

    const float* A = g_S + (size_t)k * DD * DD;
    const float* Bp = g_B + ((size_t)k * MAXM + colBase) * DD;

    int t = threadIdx.x, wid = t >> 5, lane = t & 31;
    int wm = (wid >> 2) * 64;
    int wn = (wid & 3) * 32;
    int gid = lane >> 2, tig = lane & 3;

    if (t < 128) { scY[t] = 0.f; scX[t] = 0.f; }

    float acc[4][4][4];
#pragma unroll
    for (int mt = 0; mt < 4; mt++)
#pragma unroll
        for (int nt = 0; nt < 4; nt++)
#pragma unroll
            for (int r = 0; r < 4; r++) acc[mt][nt][r] = 0.f;

    for (int c = 0; c < NCH; c++) {
        int j0 = c * KC;
#pragma unroll
        for (int e = 0; e < 4; e++) {
            int idx = t + 256 * e;
            int row = idx >> 3, c4 = idx & 7;
            *(float4*)&sA[row * LDSW + c4 * 4] =
                *(const float4*)(A + (size_t)(rowBase + row) * DD + j0 + c4 * 4);
        }
#pragma unroll
        for (int e = 0; e < 4; e++) {
            int idx = t + 256 * e;
            int row = idx >> 3, c4 = idx & 7;
            *(float4*)&sB[row * LDSW + c4 * 4] =
                *(const float4*)(Bp + (size_t)row * DD + j0 + c4 * 4);
        }
        __syncthreads();
#pragma unroll
        for (int kt = 0; kt < 4; kt++) {
            int kb = kt * 8;
            uint32_t ah[4][4], bh[4][2];
#pragma unroll
            for (int mt = 0; mt < 4; mt++) {
                int r0 = (wm + mt * 16 + gid) * LDSW + kb + tig;
                int r1 = r0 + 8 * LDSW;
                ah[mt][0] = __float_as_uint(sA[r0]);
                ah[mt][1] = __float_as_uint(sA[r1]);
                ah[mt][2] = __float_as_uint(sA[r0 + 4]);
                ah[mt][3] = __float_as_uint(sA[r1 + 4]);
            }
#pragma unroll
            for (int nt = 0; nt < 4; nt++) {
                int n0 = (wn + nt * 8 + gid) * LDSW + kb + tig;
                bh[nt][0] = __float_as_uint(sB[n0]);
                bh[nt][1] = __float_as_uint(sB[n0 + 4]);
            }
#pragma unroll
            for (int mt = 0; mt < 4; mt++)
#pragma unroll
                for (int nt = 0; nt < 4; nt++)
                    mma_tf32(acc[mt][nt], ah[mt], bh[nt]);
        }
        __syncthreads();
    }

    // ---- y^2 (no smem needed) ----
#pragma unroll
    for (int nt = 0; nt < 4; nt++) {
        float y0 = 0.f, y1 = 0.f;
#pragma unroll
        for (int mt = 0; mt < 4; mt++) {
            y0 += acc[mt][nt][0] * acc[mt][nt][0] + acc[mt][nt][2] * acc[mt][nt][2];
            y1 += acc[mt][nt][1] * acc[mt][nt][1] + acc[mt][nt][3] * acc[mt][nt][3];
        }
#pragma unroll
        for (int o = 16; o >= 4; o >>= 1) {
            y0 += __shfl_down_sync(0xffffffffu, y0, o);
            y1 += __shfl_down_sync(0xffffffffu, y1, o);
        }
        if (lane < 4) {
            atomicAdd(&scY[wn + nt * 8 + 2 * lane], y0);
            atomicAdd(&scY[wn + nt * 8 + 2 * lane + 1], y1);
        }
    }

    // ---- x.y via staged x-slice (2 halves of 64 cols, coalesced loads) ----
#pragma unroll 1
    for (int h = 0; h < 2; h++) {
        // xs[c][r] = Bp[(h*64+c)*DD + rowBase + r], c in [0,64), r in [0,128)
#pragma unroll
        for (int e = 0; e < 8; e++) {
            int idx = t + 256 * e;          // 2048 float4 slots
            int cc = idx >> 5, rq = idx & 31;
            *(float4*)&sbuf[cc * LDX + rq * 4] =
                *(const float4*)(Bp + (size_t)(h * 64 + cc) * DD + rowBase + rq * 4);
        }
        __syncthreads();
        if ((wn >> 6) == h) {
#pragma unroll
            for (int nt = 0; nt < 4; nt++) {
                int col0 = wn + nt * 8 + 2 * tig - h * 64;
                float x0 = 0.f, x1 = 0.f;
#pragma unroll
                for (int mt = 0; mt < 4; mt++) {
                    int r0 = wm + 16 * mt + gid;
                    x0 += acc[mt][nt][0] * sbuf[col0 * LDX + r0] +
                          acc[mt][nt][2] * sbuf[col0 * LDX + r0 + 8];
                    x1 += acc[mt][nt][1] * sbuf[(col0 + 1) * LDX + r0] +
                          acc[mt][nt][3] * sbuf[(col0 + 1) * LDX + r0 + 8];
                }
#pragma unroll
                for (int o = 16; o >= 4; o >>= 1) {
                    x0 += __shfl_down_sync(0xffffffffu, x0, o);
                    x1 += __shfl_down_sync(0xffffffffu, x1, o);
                }
                if (lane < 4) {
                    atomicAdd(&scX[wn + nt * 8 + 2 * lane], x0);
                    atomicAdd(&scX[wn + nt * 8 + 2 * lane + 1], x1);
                }
            }
        }
        __syncthreads();
    }

    if (t < 128) {
        int col = colBase + t;
        if (col < M) {
            atomicAdd(&g_y2[k * M + col], scY[t]);
            atomicAdd(&g_xy[k * M + col], scX[t]);
        }
    }
}

// ======================= remaining kernels =================================
__global__ void abl_assign_in(const int* __restrict__ labels,
                              const float* __restrict__ delta, int B, int N) {
    int b = blockIdx.x * blockDim.x + threadIdx.x;
    if (b >= B) return;
    int lab = labels[b];
    int cnt = g_cnt[lab];
    float best = 3.4e38f;
    int bi = 0;
    for (int i = 0; i < cnt; i++) {
        int n = g_clist[lab * MAXN + i];
        float s = g_c2[n] - 2.f * g_dotin[(size_t)b * N + n];
        if (s < best) { best = s; bi = n; }
    }
    g_ballin[b] = bi;
    g_din[b] = delta[bi];
}

// in-dist: grid (class, 6 row-chunks); S streamed once per present class.
// z_i = x_i + (S x)_i ; partial sum z^2 over this chunk's rows -> atomic.
__global__ __launch_bounds__(256) void abl_indist2(const float* __restrict__ pooled,
                                                   const float* __restrict__ cent,
                                                   int B) {
    int k = blockIdx.x;
    int rc = blockIdx.y;
    int ns = g_scnt[k];
    if (ns == 0) return;

    __shared__ float sx[4][DD];
    __shared__ int sid[4];
    const float* Sk = g_S + (size_t)k * DD * DD;
    int t = threadIdx.x, w = t >> 5, lane = t & 31;

    for (int g0 = 0; g0 < ns; g0 += 4) {
        int gcnt = min(4, ns - g0);
        if (t < 4) sid[t] = (t < gcnt) ? g_slist[k * MAXB + g0 + t] : -1;
        __syncthreads();
        for (int gi = 0; gi < gcnt; gi++) {
            int s = sid[gi];
            int bid = g_ballin[s];
            for (int j = t; j < DD; j += 256)
                sx[gi][j] = pooled[(size_t)s * DD + j] - cent[(size_t)bid * DD + j];
        }
        __syncthreads();

        float wz[4] = {0.f, 0.f, 0.f, 0.f};
        for (int ii = 0; ii < 16; ii++) {
            int i = rc * 128 + w * 16 + ii;
            const float* row = Sk + (size_t)i * DD;
            float d0 = 0.f, d1 = 0.f, d2 = 0.f, d3 = 0.f;
            for (int j = lane * 4; j < DD; j += 128) {
                float4 sv = *(const float4*)(row + j);
                float4 x0 = *(const float4*)(&sx[0][j]);
                d0 += sv.x * x0.x + sv.y * x0.y + sv.z * x0.z + sv.w * x0.w;
                if (gcnt > 1) {
                    float4 x1 = *(const float4*)(&sx[1][j]);
                    d1 += sv.x * x1.x + sv.y * x1.y + sv.z * x1.z + sv.w * x1.w;
                }
                if (gcnt > 2) {
                    float4 x2 = *(const float4*)(&sx[2][j]);
                    d2 += sv.x * x2.x + sv.y * x2.y + sv.z * x2.z + sv.w * x2.w;
                }
                if (gcnt > 3) {
                    float4 x3 = *(const float4*)(&sx[3][j]);
                    d3 += sv.x * x3.x + sv.y * x3.y + sv.z * x3.z + sv.w * x3.w;
                }
            }
#pragma unroll
            for (int o = 16; o; o >>= 1) {
                d0 += __shfl_down_sync(0xffffffffu, d0, o);
                d1 += __shfl_down_sync(0xffffffffu, d1, o);
                d2 += __shfl_down_sync(0xffffffffu, d2, o);
                d3 += __shfl_down_sync(0xffffffffu, d3, o);
            }
            if (lane == 0) {
                float dd[4] = {d0, d1, d2, d3};
                for (int gi = 0; gi < gcnt; gi++) {
                    float z = sx[gi][i] + dd[gi];
                    wz[gi] += z * z;
                }
            }
        }
        if (lane == 0)
            for (int gi = 0; gi < gcnt; gi++)
                atomicAdd(&g_eucin2[sid[gi]], wz[gi]);
        __syncthreads();
    }
}

__global__ void abl_finalize(float* __restrict__ out, int B, int M, int K, int out_size) {
    __shared__ float sred[256];
    int t = threadIdx.x;

    float pl = 0.f, pn = 0.f, nn = 0.f;
    for (int b = t; b < B; b += 256) {
        float e = sqrtf(g_eucin2[b]);
        float d = g_din[b];
        pl += (d > e) ? expf(e - d) : (e - d);
        if (e > d) pn += 1.f;
        if (e < d) nn += 1.f;
    }
    float ns = 0.f;
    for (int m = t; m < M; m += 256) {
        float s = 0.f;
        for (int k = 0; k < K; k++) {
            float e2 = g_x2[k * M + m] + 2.f * g_xy[k * M + m] + g_y2[k * M + m];
            float e = sqrtf(fmaxf(e2, 0.f));
            float d = g_dnear[k * M + m];
            s += (d > e) ? (d - e + BETA_C) : BETA_C * expf(d - e);
        }
        ns += s;
    }

    float vals[4] = {pl, pn, nn, ns};
    float red[4];
    for (int v = 0; v < 4; v++) {
        sred[t] = vals[v];
        __syncthreads();
        for (int s2 = 128; s2 > 0; s2 >>= 1) {
            if (t < s2) sred[t] += sred[t + s2];
            __syncthreads();
        }
        red[v] = sred[0];
        __syncthreads();
    }
    if (t == 0) {
        float pos_mean = red[0] / (float)B;
        float neg_mean = red[3] / (float)M;
        if (out_size > 0) out[0] = pos_mean;
        if (out_size > 1) out[1] = neg_mean;
        if (out_size > 2) out[2] = red[1];
        if (out_size > 3) out[3] = red[2];
        if (out_size > 4) out[4] = pos_mean + neg_mean;
    }
}

// ---------------------------------------------------------------------------
extern "C" void kernel_launch(void* const* d_in, const int* in_sizes, int n_in,
                              void* d_out, int out_size) {
    const float* pooled = (const float*)d_in[0];
    const float* ood    = (const float*)d_in[1];
    const float* cent   = (const float*)d_in[2];
    const float* delta  = (const float*)d_in[3];
    const float* L      = (const float*)d_in[4];
    const float* U      = (const float*)d_in[5];
    const float* Ddm    = (const float*)d_in[6];
    const int*   labels = (const int*)d_in[7];
    const int*   blab   = (const int*)d_in[8];

    int B = in_sizes[0] / DD;
    int M = in_sizes[1] / DD;
    int N = in_sizes[3];
    int K = in_sizes[6] / DD;
    int NTRI = in_sizes[4] / K;

    if (B > MAXB) B = MAXB;
    if (M > MAXM) M = MAXM;
    if (N > MAXN) N = MAXN;
    if (K > MAXK) K = MAXK;

    int ntiles = (DD / 32) * (DD / 32 + 1) / 2;   // 300
    int totf = (B + M) * N;                        // assumes B*N then M*N halves
    int zblocks = (totf + 511) / 512;

    abl_clist_all<<<1, 256>>>(blab, labels, N, K, B);                                // 1
    abl_c2zero<<<N + zblocks, 128>>>(cent, N, totf);                                 // 2
    abl_build_S<<<dim3(ntiles, K), 256>>>(L, U, Ddm, NTRI);                          // 3
    abl_dot_comb<<<dim3((N + 63) / 64, (B + M) / 64, 4), 256>>>(pooled, ood, cent, B, M, N); // 4
    abl_near_b<<<dim3(K, (M + 63) / 64), 256>>>(ood, cent, delta, M, N);             // 5
    abl_ood_s2<<<dim3((M + 127) / 128, DD / 128, K), 256>>>(M);                      // 6 <- profiled
    abl_assign_in<<<(B + 255) / 256, 256>>>(labels, delta, B, N);                    // 7
    abl_indist2<<<dim3(K, DD / 128), 256>>>(pooled, cent, B);                        // 8
    abl_finalize<<<1, 256>>>((float*)d_out, B, M, K, out_size);                      // 9
}